// round 2
// baseline (speedup 1.0000x reference)
#include <cuda_runtime.h>

#define NMAX 100000
#define EMAX 2000000

// Scratch (no allocations allowed — __device__ globals)
__device__ __align__(128) float g_bufA[NMAX * 32];  // xw (messages to gather)
__device__ __align__(128) float g_bufB[NMAX * 32];  // agg (scatter target)
__device__ float g_dinv[NMAX];                      // deg accumulator -> dinv
__device__ float g_nrm[EMAX];                       // per-edge norm coefficient

// ---------------------------------------------------------------------------
// Zero agg buffer; init degree accumulator to 1.0 (self-loop weight)
__global__ void zero_kernel(int n) {
    int i = blockIdx.x * blockDim.x + threadIdx.x;
    if (i < n * 8) ((float4*)g_bufB)[i] = make_float4(0.f, 0.f, 0.f, 0.f);
    if (i < n) g_dinv[i] = 1.0f;
}

// deg[col] += ew  (weighted in-degree at targets)
__global__ void deg_kernel(const int* __restrict__ ei, const float* __restrict__ ew, int E) {
    int e = blockIdx.x * blockDim.x + threadIdx.x;
    if (e >= E) return;
    atomicAdd(&g_dinv[ei[E + e]], ew[e]);
}

// dinv = rsqrt(deg)   (deg >= 1 always, thanks to self-loop weight)
__global__ void dinv_kernel(int n) {
    int i = blockIdx.x * blockDim.x + threadIdx.x;
    if (i < n) g_dinv[i] = rsqrtf(g_dinv[i]);
}

// per-edge norm = dinv[row] * ew * dinv[col]   (shared across both GCN layers)
__global__ void norm_kernel(const int* __restrict__ ei, const float* __restrict__ ew, int E) {
    int e = blockIdx.x * blockDim.x + threadIdx.x;
    if (e >= E) return;
    int r = ei[e];
    int c = ei[E + e];
    g_nrm[e] = g_dinv[r] * ew[e] * g_dinv[c];
}

// ---------------------------------------------------------------------------
// Per-node: emb = relu(c@We1+be1)@We2+be2 ; feat=[x,emb] ; bufA = feat@W1
__global__ void embed_kernel(const float* __restrict__ x, const float* __restrict__ c,
                             const float* __restrict__ We1, const float* __restrict__ be1,
                             const float* __restrict__ We2, const float* __restrict__ be2,
                             const float* __restrict__ W1, int n) {
    __shared__ float4 sPack[128];   // {We1[0][j], We1[1][j], be1[j], 0}
    __shared__ float4 sWe2[512];    // [128][16] as float4
    __shared__ float  sbe2[16];
    __shared__ float4 sW1[152];     // [19][32] as float4

    for (int j = threadIdx.x; j < 128; j += blockDim.x)
        sPack[j] = make_float4(We1[j], We1[128 + j], be1[j], 0.f);
    for (int j = threadIdx.x; j < 512; j += blockDim.x)
        sWe2[j] = ((const float4*)We2)[j];
    if (threadIdx.x < 16) sbe2[threadIdx.x] = be2[threadIdx.x];
    for (int j = threadIdx.x; j < 152; j += blockDim.x)
        sW1[j] = ((const float4*)W1)[j];
    __syncthreads();

    int i = blockIdx.x * blockDim.x + threadIdx.x;
    if (i >= n) return;

    float c0 = c[2 * i], c1 = c[2 * i + 1];
    float emb[16];
#pragma unroll
    for (int k = 0; k < 16; k++) emb[k] = sbe2[k];

#pragma unroll 4
    for (int j = 0; j < 128; j++) {
        float4 p = sPack[j];
        float h = fmaxf(fmaf(c0, p.x, fmaf(c1, p.y, p.z)), 0.f);
#pragma unroll
        for (int q = 0; q < 4; q++) {
            float4 w = sWe2[j * 4 + q];
            emb[4 * q + 0] = fmaf(h, w.x, emb[4 * q + 0]);
            emb[4 * q + 1] = fmaf(h, w.y, emb[4 * q + 1]);
            emb[4 * q + 2] = fmaf(h, w.z, emb[4 * q + 2]);
            emb[4 * q + 3] = fmaf(h, w.w, emb[4 * q + 3]);
        }
    }

    float feat[19];
    feat[0] = x[3 * i]; feat[1] = x[3 * i + 1]; feat[2] = x[3 * i + 2];
#pragma unroll
    for (int k = 0; k < 16; k++) feat[3 + k] = emb[k];

    float4 acc[8];
#pragma unroll
    for (int q = 0; q < 8; q++) acc[q] = make_float4(0.f, 0.f, 0.f, 0.f);
#pragma unroll
    for (int r = 0; r < 19; r++) {
        float f = feat[r];
#pragma unroll
        for (int q = 0; q < 8; q++) {
            float4 w = sW1[r * 8 + q];
            acc[q].x = fmaf(f, w.x, acc[q].x);
            acc[q].y = fmaf(f, w.y, acc[q].y);
            acc[q].z = fmaf(f, w.z, acc[q].z);
            acc[q].w = fmaf(f, w.w, acc[q].w);
        }
    }
    float4* outp = (float4*)&g_bufA[(size_t)i * 32];
#pragma unroll
    for (int q = 0; q < 8; q++) outp[q] = acc[q];
}

// ---------------------------------------------------------------------------
// Scatter: 8 threads per edge; each handles one float4 chunk of the 32-wide row.
// bufB[col] += nrm[e] * bufA[row]  via vector reduction (no return value)
__global__ void scatter_kernel(const int* __restrict__ ei, int E) {
    int t = blockIdx.x * blockDim.x + threadIdx.x;
    int e = t >> 3;
    int q = t & 7;
    if (e >= E) return;
    int r = ei[e];
    int c = ei[E + e];
    float nrm = g_nrm[e];
    float4 v = ((const float4*)g_bufA)[(size_t)r * 8 + q];
    float vx = v.x * nrm, vy = v.y * nrm, vz = v.z * nrm, vw = v.w * nrm;
    float4* dst = ((float4*)g_bufB) + (size_t)c * 8 + q;
    asm volatile("red.global.add.v4.f32 [%0], {%1,%2,%3,%4};"
                 :: "l"(dst), "f"(vx), "f"(vy), "f"(vz), "f"(vw)
                 : "memory");
}

// ---------------------------------------------------------------------------
// Mid layer: h1 = relu(agg + dinv^2*xw + b1); bufA = h1@W2; zero bufB for layer 2
__global__ void mid_kernel(const float* __restrict__ b1, const float* __restrict__ W2, int n) {
    __shared__ float4 sW2[256];  // [32][32] as float4
    __shared__ float  sb1[32];
    for (int j = threadIdx.x; j < 256; j += blockDim.x) sW2[j] = ((const float4*)W2)[j];
    if (threadIdx.x < 32) sb1[threadIdx.x] = b1[threadIdx.x];
    __syncthreads();

    int i = blockIdx.x * blockDim.x + threadIdx.x;
    if (i >= n) return;

    float d = g_dinv[i];
    float s = d * d;
    float4* aggp = (float4*)&g_bufB[(size_t)i * 32];
    float4* xwp  = (float4*)&g_bufA[(size_t)i * 32];

    float h[32];
#pragma unroll
    for (int q = 0; q < 8; q++) {
        float4 a  = aggp[q];
        float4 xv = xwp[q];
        h[4 * q + 0] = fmaxf(fmaf(s, xv.x, a.x) + sb1[4 * q + 0], 0.f);
        h[4 * q + 1] = fmaxf(fmaf(s, xv.y, a.y) + sb1[4 * q + 1], 0.f);
        h[4 * q + 2] = fmaxf(fmaf(s, xv.z, a.z) + sb1[4 * q + 2], 0.f);
        h[4 * q + 3] = fmaxf(fmaf(s, xv.w, a.w) + sb1[4 * q + 3], 0.f);
    }

    float4 acc[8];
#pragma unroll
    for (int q = 0; q < 8; q++) acc[q] = make_float4(0.f, 0.f, 0.f, 0.f);
#pragma unroll
    for (int m = 0; m < 32; m++) {
        float f = h[m];
#pragma unroll
        for (int q = 0; q < 8; q++) {
            float4 w = sW2[m * 8 + q];
            acc[q].x = fmaf(f, w.x, acc[q].x);
            acc[q].y = fmaf(f, w.y, acc[q].y);
            acc[q].z = fmaf(f, w.z, acc[q].z);
            acc[q].w = fmaf(f, w.w, acc[q].w);
        }
    }
#pragma unroll
    for (int q = 0; q < 8; q++) {
        xwp[q]  = acc[q];
        aggp[q] = make_float4(0.f, 0.f, 0.f, 0.f);
    }
}

// ---------------------------------------------------------------------------
// Final: h2 = relu(agg + dinv^2*xw + b2); out = h2 @ Wfc + bfc
__global__ void final_kernel(const float* __restrict__ b2, const float* __restrict__ Wfc,
                             const float* __restrict__ bfc, float* __restrict__ out, int n) {
    __shared__ float sWfc[32];
    __shared__ float sb2[32];
    __shared__ float sbfc;
    if (threadIdx.x < 32) { sWfc[threadIdx.x] = Wfc[threadIdx.x]; sb2[threadIdx.x] = b2[threadIdx.x]; }
    if (threadIdx.x == 0) sbfc = bfc[0];
    __syncthreads();

    int i = blockIdx.x * blockDim.x + threadIdx.x;
    if (i >= n) return;

    float d = g_dinv[i];
    float s = d * d;
    const float4* aggp = (const float4*)&g_bufB[(size_t)i * 32];
    const float4* xwp  = (const float4*)&g_bufA[(size_t)i * 32];

    float acc = sbfc;
#pragma unroll
    for (int q = 0; q < 8; q++) {
        float4 a  = aggp[q];
        float4 xv = xwp[q];
        acc = fmaf(fmaxf(fmaf(s, xv.x, a.x) + sb2[4 * q + 0], 0.f), sWfc[4 * q + 0], acc);
        acc = fmaf(fmaxf(fmaf(s, xv.y, a.y) + sb2[4 * q + 1], 0.f), sWfc[4 * q + 1], acc);
        acc = fmaf(fmaxf(fmaf(s, xv.z, a.z) + sb2[4 * q + 2], 0.f), sWfc[4 * q + 2], acc);
        acc = fmaf(fmaxf(fmaf(s, xv.w, a.w) + sb2[4 * q + 3], 0.f), sWfc[4 * q + 3], acc);
    }
    out[i] = acc;
}

// ---------------------------------------------------------------------------
extern "C" void kernel_launch(void* const* d_in, const int* in_sizes, int n_in,
                              void* d_out, int out_size) {
    const float* x   = (const float*)d_in[0];
    const float* c   = (const float*)d_in[1];
    const int*   ei  = (const int*)d_in[2];
    const float* ew  = (const float*)d_in[3];
    const float* We1 = (const float*)d_in[4];
    const float* be1 = (const float*)d_in[5];
    const float* We2 = (const float*)d_in[6];
    const float* be2 = (const float*)d_in[7];
    const float* W1  = (const float*)d_in[8];
    const float* b1  = (const float*)d_in[9];
    const float* W2  = (const float*)d_in[10];
    const float* b2  = (const float*)d_in[11];
    const float* Wfc = (const float*)d_in[12];
    const float* bfc = (const float*)d_in[13];

    int n = in_sizes[1] / 2;   // c is [N, 2]
    int E = in_sizes[3];       // ew is [E]
    const int TB = 256;

    zero_kernel<<<(n * 8 + TB - 1) / TB, TB>>>(n);
    deg_kernel<<<(E + TB - 1) / TB, TB>>>(ei, ew, E);
    dinv_kernel<<<(n + TB - 1) / TB, TB>>>(n);
    norm_kernel<<<(E + TB - 1) / TB, TB>>>(ei, ew, E);
    embed_kernel<<<(n + TB - 1) / TB, TB>>>(x, c, We1, be1, We2, be2, W1, n);
    scatter_kernel<<<(E * 8 + TB - 1) / TB, TB>>>(ei, E);     // layer 1 aggregation
    mid_kernel<<<(n + TB - 1) / TB, TB>>>(b1, W2, n);
    scatter_kernel<<<(E * 8 + TB - 1) / TB, TB>>>(ei, E);     // layer 2 aggregation
    final_kernel<<<(n + TB - 1) / TB, TB>>>(b2, Wfc, bfc, (float*)d_out, n);
}